// round 4
// baseline (speedup 1.0000x reference)
#include <cuda_runtime.h>
#include <cuda_fp16.h>
#include <cstdint>

// Problem constants (fixed by the dataset)
#define PM 4
#define PK 8192
#define PKK (PK/2)            // 4096 packed-k rows
#define PN 28672
#define PG 128                // group size (k elements)
// Geometry
#define THREADS 256
#define COLS_PER_THREAD 4
#define COLS_PER_CTA (THREADS*COLS_PER_THREAD)   // 1024
#define NB (PN/COLS_PER_CTA)                     // 28
#define KSPLIT 16
#define KK_PER_SPLIT (PKK/KSPLIT)                // 256
#define GROUPS_PER_SPLIT (KK_PER_SPLIT/(PG/2))   // 4

// Split-K partials: [KSPLIT][M][N] fp32. Static device global (no allocation).
__device__ float g_scratch[KSPLIT * PM * PN];

__global__ void __launch_bounds__(THREADS)
int4gemv_main(const float* __restrict__ x,      // fp16 promoted to f32 by harness
              const int*   __restrict__ w,
              const float* __restrict__ scales) // fp16 promoted to f32 by harness
{
    __shared__ float xs[KK_PER_SPLIT * 8];   // [kk_local][m*2 + (k parity)], 8KB

    const int tid     = threadIdx.x;
    const int ks      = blockIdx.y;
    const int kk0     = ks * KK_PER_SPLIT;
    const int colBase = blockIdx.x * COLS_PER_CTA + tid * COLS_PER_THREAD;

    // Preload this split's x slice (already f32).
    // Layout per kk: [x0_even, x0_odd, x1_even, x1_odd, x2_e, x2_o, x3_e, x3_o]
    for (int i = tid; i < KK_PER_SPLIT * 8; i += THREADS) {
        int kkl = i >> 3;
        int r   = i & 7;
        int m   = r >> 1;
        int j   = r & 1;
        xs[i] = x[m * PK + 2 * (kk0 + kkl) + j];
    }
    __syncthreads();

    float acc[COLS_PER_THREAD][PM];
    #pragma unroll
    for (int c = 0; c < COLS_PER_THREAD; ++c)
        #pragma unroll
        for (int m = 0; m < PM; ++m) acc[c][m] = 0.f;

    const int* wp = w + (size_t)kk0 * PN + colBase;
    const __half2 c1032 = __half2half2(__ushort_as_half((unsigned short)0x6408)); // 1032.0h

    for (int g = 0; g < GROUPS_PER_SPLIT; ++g) {
        // Scale row for this group: 4 contiguous f32 scales (exact fp16 values).
        const int grow = ks * GROUPS_PER_SPLIT + g;
        float4 sv = *reinterpret_cast<const float4*>(scales + (size_t)grow * PN + colBase);
        __half2 s2[COLS_PER_THREAD];
        s2[0] = __half2half2(__float2half_rn(sv.x));
        s2[1] = __half2half2(__float2half_rn(sv.y));
        s2[2] = __half2half2(__float2half_rn(sv.z));
        s2[3] = __half2half2(__float2half_rn(sv.w));

        #pragma unroll 4
        for (int kkl = 0; kkl < PG/2; ++kkl) {
            // 4 packed words = this thread's 4 columns at this kk (coalesced LDG.128)
            int4 wv = *reinterpret_cast<const int4*>(wp);
            wp += PN;

            const float4* xp = reinterpret_cast<const float4*>(&xs[(g * (PG/2) + kkl) * 8]);
            float4 xa = xp[0];   // rows 0,1: (x0e, x0o, x1e, x1o)
            float4 xb = xp[1];   // rows 2,3

            int wb[4] = {wv.x, wv.y, wv.z, wv.w};
            #pragma unroll
            for (int c = 0; c < 4; ++c) {
                // nibble -> fp16 magic: (0x6400 | nib) = 1024 + nib ; exact -1032 => nib-8
                unsigned int b = (unsigned int)wb[c];
                unsigned int t = (((b << 12) | b) & 0x000F000Fu) | 0x64006400u;
                __half2 h2 = *reinterpret_cast<__half2*>(&t);
                __half2 w2 = __hsub2(h2, c1032);     // exact: (w-8) in fp16
                __half2 dq = __hmul2(w2, s2[c]);     // fp16 round == reference deq
                float d0 = __half2float(__low2half(dq));   // even k
                float d1 = __half2float(__high2half(dq));  // odd  k

                acc[c][0] = fmaf(xa.x, d0, acc[c][0]);
                acc[c][0] = fmaf(xa.y, d1, acc[c][0]);
                acc[c][1] = fmaf(xa.z, d0, acc[c][1]);
                acc[c][1] = fmaf(xa.w, d1, acc[c][1]);
                acc[c][2] = fmaf(xb.x, d0, acc[c][2]);
                acc[c][2] = fmaf(xb.y, d1, acc[c][2]);
                acc[c][3] = fmaf(xb.z, d0, acc[c][3]);
                acc[c][3] = fmaf(xb.w, d1, acc[c][3]);
            }
        }
    }

    // Write split partials (coalesced float4 per row).
    float* sc = g_scratch + (size_t)ks * PM * PN;
    #pragma unroll
    for (int m = 0; m < PM; ++m) {
        float4 v = make_float4(acc[0][m], acc[1][m], acc[2][m], acc[3][m]);
        *reinterpret_cast<float4*>(sc + m * PN + colBase) = v;
    }
}

__global__ void int4gemv_reduce(const float* __restrict__ bias,
                                float* __restrict__ out)
{
    int idx = blockIdx.x * blockDim.x + threadIdx.x;
    if (idx >= PM * PN) return;
    float s = 0.f;
    #pragma unroll
    for (int ks = 0; ks < KSPLIT; ++ks)
        s += g_scratch[ks * PM * PN + idx];
    int n = idx % PN;
    // Match reference exactly: f32 -> fp16 round, fp16 bias add, back to f32.
    __half h = __float2half_rn(s);
    __half b = __float2half_rn(bias[n]);
    out[idx] = __half2float(__hadd(h, b));
}

extern "C" void kernel_launch(void* const* d_in, const int* in_sizes, int n_in,
                              void* d_out, int out_size)
{
    // Bind inputs BY ELEMENT COUNT (dtype-invariant, robust to ordering):
    //   x:             4*8192      = 32768
    //   weight_packed: 4096*28672  = 117440512
    //   scales:        224*28672   = 6422528
    //   bias:          28672
    //   group_size:    1 (ignored)
    const float* x      = nullptr;
    const int*   w      = nullptr;
    const float* scales = nullptr;
    const float* bias   = nullptr;

    for (int i = 0; i < n_in; ++i) {
        switch (in_sizes[i]) {
            case PM * PK:        x      = (const float*)d_in[i]; break;
            case PKK * PN:       w      = (const int*)  d_in[i]; break;
            case (PK/PG) * PN:   scales = (const float*)d_in[i]; break;
            case PN:             bias   = (const float*)d_in[i]; break;
            default: break; // group_size scalar etc.
        }
    }

    float* out = (float*)d_out;

    dim3 grid(NB, KSPLIT);
    int4gemv_main<<<grid, THREADS>>>(x, w, scales);

    int tot = PM * PN;
    int4gemv_reduce<<<(tot + 255) / 256, 256>>>(bias, out);
}

// round 5
// speedup vs baseline: 1.0594x; 1.0594x over previous
#include <cuda_runtime.h>
#include <cuda_fp16.h>
#include <cstdint>

// Problem constants (fixed by the dataset)
#define PM 4
#define PK 8192
#define PKK (PK/2)            // 4096 packed-k rows
#define PN 28672
#define PG 128                // group size (k elements)
// Geometry
#define THREADS 256
#define COLS_PER_THREAD 4
#define COLS_PER_CTA (THREADS*COLS_PER_THREAD)   // 1024
#define NB (PN/COLS_PER_CTA)                     // 28
#define KSPLIT 16
#define KK_PER_SPLIT (PKK/KSPLIT)                // 256
#define GROUPS_PER_SPLIT (KK_PER_SPLIT/(PG/2))   // 4

// Split-K partials: [KSPLIT][M][N] fp32. Static device global (no allocation).
__device__ float g_scratch[KSPLIT * PM * PN];

// Packed f32x2 FMA (Blackwell, PTX-only — halves FFMA issue count)
__device__ __forceinline__ void fma_f32x2(unsigned long long& acc,
                                          unsigned long long a,
                                          unsigned long long b) {
    asm("fma.rn.f32x2 %0, %1, %2, %0;" : "+l"(acc) : "l"(a), "l"(b));
}
__device__ __forceinline__ unsigned long long pack_f32x2(float lo, float hi) {
    unsigned long long r;
    asm("mov.b64 %0, {%1, %2};" : "=l"(r) : "f"(lo), "f"(hi));
    return r;
}
__device__ __forceinline__ void unpack_f32x2(unsigned long long v, float& lo, float& hi) {
    asm("mov.b64 {%0, %1}, %2;" : "=f"(lo), "=f"(hi) : "l"(v));
}

__global__ void __launch_bounds__(THREADS)
int4gemv_main(const float* __restrict__ x,      // fp16 promoted to f32 by harness
              const int*   __restrict__ w,
              const float* __restrict__ scales) // fp16 promoted to f32 by harness
{
    // Per kk: 4 packed (x_even, x_odd) f32 pairs, one per m-row. 64-bit aligned.
    __shared__ unsigned long long xs2[KK_PER_SPLIT * 4];   // 8KB

    const int tid     = threadIdx.x;
    const int ks      = blockIdx.y;
    const int kk0     = ks * KK_PER_SPLIT;
    const int colBase = blockIdx.x * COLS_PER_CTA + tid * COLS_PER_THREAD;

    // Preload x slice: xs2[kk*4 + m] = (x[m][2kk], x[m][2kk+1])
    {
        float* xsf = reinterpret_cast<float*>(xs2);
        for (int i = tid; i < KK_PER_SPLIT * 8; i += THREADS) {
            int kkl = i >> 3;
            int r   = i & 7;
            int m   = r >> 1;
            int j   = r & 1;
            xsf[(kkl * 4 + m) * 2 + j] = x[m * PK + 2 * (kk0 + kkl) + j];
        }
    }
    __syncthreads();

    // acc2[c][m] = (sum over even k, sum over odd k) as packed f32x2
    unsigned long long acc2[COLS_PER_THREAD][PM];
    #pragma unroll
    for (int c = 0; c < COLS_PER_THREAD; ++c)
        #pragma unroll
        for (int m = 0; m < PM; ++m) acc2[c][m] = 0ull;

    const int* wp = w + (size_t)kk0 * PN + colBase;
    const __half2 c1032 = __half2half2(__ushort_as_half((unsigned short)0x6408)); // 1032.0h

    for (int g = 0; g < GROUPS_PER_SPLIT; ++g) {
        // 4 contiguous f32 scales (exact fp16 values) for this thread's columns.
        const int grow = ks * GROUPS_PER_SPLIT + g;
        float4 sv = *reinterpret_cast<const float4*>(scales + (size_t)grow * PN + colBase);
        __half2 s2[COLS_PER_THREAD];
        s2[0] = __half2half2(__float2half_rn(sv.x));
        s2[1] = __half2half2(__float2half_rn(sv.y));
        s2[2] = __half2half2(__float2half_rn(sv.z));
        s2[3] = __half2half2(__float2half_rn(sv.w));

        #pragma unroll 4
        for (int kkl = 0; kkl < PG/2; ++kkl) {
            // 4 packed words = this thread's 4 columns at this kk (coalesced LDG.128)
            int4 wv = *reinterpret_cast<const int4*>(wp);
            wp += PN;

            const unsigned long long* xp = &xs2[(g * (PG/2) + kkl) * 4];
            unsigned long long xm0 = xp[0];
            unsigned long long xm1 = xp[1];
            unsigned long long xm2 = xp[2];
            unsigned long long xm3 = xp[3];

            int wb[4] = {wv.x, wv.y, wv.z, wv.w};
            #pragma unroll
            for (int c = 0; c < 4; ++c) {
                // nibble -> fp16 magic: (0x6400 | nib) = 1024 + nib ; exact -1032 => nib-8
                unsigned int b = (unsigned int)wb[c];
                unsigned int t = (((b << 12) | b) & 0x000F000Fu) | 0x64006400u;
                __half2 h2 = *reinterpret_cast<__half2*>(&t);
                __half2 w2 = __hsub2(h2, c1032);     // exact: (w-8) in fp16
                __half2 dq = __hmul2(w2, s2[c]);     // fp16 round == reference deq
                float d0 = __half2float(__low2half(dq));   // even k
                float d1 = __half2float(__high2half(dq));  // odd  k
                unsigned long long d64 = pack_f32x2(d0, d1);

                fma_f32x2(acc2[c][0], xm0, d64);
                fma_f32x2(acc2[c][1], xm1, d64);
                fma_f32x2(acc2[c][2], xm2, d64);
                fma_f32x2(acc2[c][3], xm3, d64);
            }
        }
    }

    // Collapse even/odd halves and write split partials (coalesced float4 per row).
    float* sc = g_scratch + (size_t)ks * PM * PN;
    #pragma unroll
    for (int m = 0; m < PM; ++m) {
        float r[4];
        #pragma unroll
        for (int c = 0; c < 4; ++c) {
            float lo, hi;
            unpack_f32x2(acc2[c][m], lo, hi);
            r[c] = lo + hi;
        }
        float4 v = make_float4(r[0], r[1], r[2], r[3]);
        *reinterpret_cast<float4*>(sc + m * PN + colBase) = v;
    }
}

__global__ void int4gemv_reduce(const float* __restrict__ bias,
                                float* __restrict__ out)
{
    // Each thread produces 4 contiguous outputs (float4 I/O).
    int idx4 = blockIdx.x * blockDim.x + threadIdx.x;
    if (idx4 >= (PM * PN) / 4) return;
    int base = idx4 * 4;

    float4 s = make_float4(0.f, 0.f, 0.f, 0.f);
    #pragma unroll
    for (int ks = 0; ks < KSPLIT; ++ks) {
        float4 p = *reinterpret_cast<const float4*>(&g_scratch[ks * PM * PN + base]);
        s.x += p.x; s.y += p.y; s.z += p.z; s.w += p.w;
    }
    int n = base % PN;   // PN % 4 == 0, so the 4 lanes are n..n+3
    float4 bv = *reinterpret_cast<const float4*>(&bias[n]);

    // Match reference exactly: f32 -> fp16 round, fp16 bias add, back to f32.
    float4 o;
    o.x = __half2float(__hadd(__float2half_rn(s.x), __float2half_rn(bv.x)));
    o.y = __half2float(__hadd(__float2half_rn(s.y), __float2half_rn(bv.y)));
    o.z = __half2float(__hadd(__float2half_rn(s.z), __float2half_rn(bv.z)));
    o.w = __half2float(__hadd(__float2half_rn(s.w), __float2half_rn(bv.w)));
    *reinterpret_cast<float4*>(&out[base]) = o;
}

extern "C" void kernel_launch(void* const* d_in, const int* in_sizes, int n_in,
                              void* d_out, int out_size)
{
    // Bind inputs BY ELEMENT COUNT (dtype-invariant, robust to ordering):
    //   x: 32768, weight_packed: 117440512, scales: 6422528, bias: 28672
    const float* x      = nullptr;
    const int*   w      = nullptr;
    const float* scales = nullptr;
    const float* bias   = nullptr;

    for (int i = 0; i < n_in; ++i) {
        switch (in_sizes[i]) {
            case PM * PK:        x      = (const float*)d_in[i]; break;
            case PKK * PN:       w      = (const int*)  d_in[i]; break;
            case (PK/PG) * PN:   scales = (const float*)d_in[i]; break;
            case PN:             bias   = (const float*)d_in[i]; break;
            default: break; // group_size scalar etc.
        }
    }

    float* out = (float*)d_out;

    dim3 grid(NB, KSPLIT);
    int4gemv_main<<<grid, THREADS>>>(x, w, scales);

    int tot4 = (PM * PN) / 4;
    int4gemv_reduce<<<(tot4 + 255) / 256, 256>>>(bias, out);
}

// round 6
// speedup vs baseline: 1.2563x; 1.1858x over previous
#include <cuda_runtime.h>
#include <cuda_fp16.h>
#include <cstdint>

// Problem constants (fixed by the dataset)
#define PM 4
#define PK 8192
#define PKK (PK/2)            // 4096 packed-k rows
#define PN 28672
#define PG 128                // group size (k elements)
// Geometry
#define THREADS 256
#define COLS_PER_THREAD 4
#define COLS_PER_CTA (THREADS*COLS_PER_THREAD)   // 1024
#define NB (PN/COLS_PER_CTA)                     // 28
#define KSPLIT 32
#define KK_PER_SPLIT (PKK/KSPLIT)                // 128
#define GROUPS_PER_SPLIT (KK_PER_SPLIT/(PG/2))   // 2
#define BATCH 4
#define NBATCH (KK_PER_SPLIT/BATCH)              // 32
#define BATCHES_PER_GROUP ((PG/2)/BATCH)         // 16

// Split-K partials: [KSPLIT][M][N] fp32. Static device global (no allocation).
__device__ float g_scratch[KSPLIT * PM * PN];

// Packed f32x2 FMA (Blackwell, PTX-only)
__device__ __forceinline__ void fma_f32x2(unsigned long long& acc,
                                          unsigned long long a,
                                          unsigned long long b) {
    asm("fma.rn.f32x2 %0, %1, %2, %0;" : "+l"(acc) : "l"(a), "l"(b));
}
__device__ __forceinline__ unsigned long long pack_f32x2(float lo, float hi) {
    unsigned long long r;
    asm("mov.b64 %0, {%1, %2};" : "=l"(r) : "f"(lo), "f"(hi));
    return r;
}
__device__ __forceinline__ void unpack_f32x2(unsigned long long v, float& lo, float& hi) {
    asm("mov.b64 {%0, %1}, %2;" : "=f"(lo), "=f"(hi) : "l"(v));
}

__global__ void __launch_bounds__(THREADS, 2)
int4gemv_main(const float* __restrict__ x,      // fp16 promoted to f32 by harness
              const int*   __restrict__ w,
              const float* __restrict__ scales) // fp16 promoted to f32 by harness
{
    // Per kk: 4 packed (x_even, x_odd) f32 pairs, one per m-row.
    __shared__ unsigned long long xs2[KK_PER_SPLIT * 4];   // 4KB

    const int tid     = threadIdx.x;
    const int ks      = blockIdx.y;
    const int kk0     = ks * KK_PER_SPLIT;
    const int colBase = blockIdx.x * COLS_PER_CTA + tid * COLS_PER_THREAD;

    // Preload x slice: xs2[kk*4 + m] = (x[m][2kk], x[m][2kk+1])
    {
        float* xsf = reinterpret_cast<float*>(xs2);
        for (int i = tid; i < KK_PER_SPLIT * 8; i += THREADS) {
            int kkl = i >> 3;
            int r   = i & 7;
            int m   = r >> 1;
            int j   = r & 1;
            xsf[(kkl * 4 + m) * 2 + j] = x[m * PK + 2 * (kk0 + kkl) + j];
        }
    }
    __syncthreads();

    // acc2[c][m] = (sum over even k, sum over odd k) as packed f32x2
    unsigned long long acc2[COLS_PER_THREAD][PM];
    #pragma unroll
    for (int c = 0; c < COLS_PER_THREAD; ++c)
        #pragma unroll
        for (int m = 0; m < PM; ++m) acc2[c][m] = 0ull;

    const int* wp = w + (size_t)kk0 * PN + colBase;
    const __half2 c1032 = __half2half2(__ushort_as_half((unsigned short)0x6408)); // 1032.0h

    // Software-pipelined: double-buffered batches of 4 int4 loads.
    int4 buf[2][BATCH];

    // Prologue: load batch 0.
    #pragma unroll
    for (int j = 0; j < BATCH; ++j)
        buf[0][j] = *reinterpret_cast<const int4*>(wp + j * PN);
    wp += BATCH * PN;

    // May we prefetch one batch past this split's end? (Reads the next split's
    // rows — valid memory — except for the very last split.)
    const bool tail_ok = (ks != KSPLIT - 1);

    __half2 s2[COLS_PER_THREAD];
    #pragma unroll
    for (int b = 0; b < NBATCH; ++b) {
        const int pb = b & 1;
        const int nb2 = pb ^ 1;

        // Refresh scales at group boundaries (compile-time condition after unroll).
        if ((b & (BATCHES_PER_GROUP - 1)) == 0) {
            const int grow = ks * GROUPS_PER_SPLIT + (b / BATCHES_PER_GROUP);
            float4 sv = *reinterpret_cast<const float4*>(scales + (size_t)grow * PN + colBase);
            s2[0] = __half2half2(__float2half_rn(sv.x));
            s2[1] = __half2half2(__float2half_rn(sv.y));
            s2[2] = __half2half2(__float2half_rn(sv.z));
            s2[3] = __half2half2(__float2half_rn(sv.w));
        }

        // Prefetch next batch while computing this one.
        if (b + 1 < NBATCH) {
            #pragma unroll
            for (int j = 0; j < BATCH; ++j)
                buf[nb2][j] = *reinterpret_cast<const int4*>(wp + j * PN);
            wp += BATCH * PN;
        } else if (tail_ok) {
            #pragma unroll
            for (int j = 0; j < BATCH; ++j)
                buf[nb2][j] = *reinterpret_cast<const int4*>(wp + j * PN);
        }

        // Compute batch b: 4 consecutive kk rows.
        #pragma unroll
        for (int j = 0; j < BATCH; ++j) {
            const int kkl = b * BATCH + j;
            const unsigned long long* xp = &xs2[kkl * 4];
            unsigned long long xm0 = xp[0];
            unsigned long long xm1 = xp[1];
            unsigned long long xm2 = xp[2];
            unsigned long long xm3 = xp[3];

            int4 wv = buf[pb][j];
            int wb[4] = {wv.x, wv.y, wv.z, wv.w};
            #pragma unroll
            for (int c = 0; c < 4; ++c) {
                // nibble -> fp16 magic: (0x6400 | nib) = 1024 + nib ; exact -1032 => nib-8
                unsigned int bb = (unsigned int)wb[c];
                unsigned int t = (((bb << 12) | bb) & 0x000F000Fu) | 0x64006400u;
                __half2 h2 = *reinterpret_cast<__half2*>(&t);
                __half2 w2 = __hsub2(h2, c1032);     // exact: (w-8) in fp16
                __half2 dq = __hmul2(w2, s2[c]);     // fp16 round == reference deq
                float d0 = __half2float(__low2half(dq));   // even k
                float d1 = __half2float(__high2half(dq));  // odd  k
                unsigned long long d64 = pack_f32x2(d0, d1);

                fma_f32x2(acc2[c][0], xm0, d64);
                fma_f32x2(acc2[c][1], xm1, d64);
                fma_f32x2(acc2[c][2], xm2, d64);
                fma_f32x2(acc2[c][3], xm3, d64);
            }
        }
    }

    // Collapse even/odd halves and write split partials (coalesced float4 per row).
    float* sc = g_scratch + (size_t)ks * PM * PN;
    #pragma unroll
    for (int m = 0; m < PM; ++m) {
        float r[4];
        #pragma unroll
        for (int c = 0; c < 4; ++c) {
            float lo, hi;
            unpack_f32x2(acc2[c][m], lo, hi);
            r[c] = lo + hi;
        }
        float4 v = make_float4(r[0], r[1], r[2], r[3]);
        *reinterpret_cast<float4*>(sc + m * PN + colBase) = v;
    }
}

__global__ void __launch_bounds__(256)
int4gemv_reduce(const float* __restrict__ bias,
                float* __restrict__ out)
{
    // One output element per thread: 448 CTAs, 32 independent coalesced loads each.
    int idx = blockIdx.x * blockDim.x + threadIdx.x;
    if (idx >= PM * PN) return;

    float s = 0.f;
    #pragma unroll
    for (int ks = 0; ks < KSPLIT; ++ks)
        s += g_scratch[ks * PM * PN + idx];

    int n = idx % PN;
    // Match reference exactly: f32 -> fp16 round, fp16 bias add, back to f32.
    __half h = __float2half_rn(s);
    __half b = __float2half_rn(bias[n]);
    out[idx] = __half2float(__hadd(h, b));
}

extern "C" void kernel_launch(void* const* d_in, const int* in_sizes, int n_in,
                              void* d_out, int out_size)
{
    // Bind inputs BY ELEMENT COUNT (dtype-invariant, robust to ordering):
    //   x: 32768, weight_packed: 117440512, scales: 6422528, bias: 28672
    const float* x      = nullptr;
    const int*   w      = nullptr;
    const float* scales = nullptr;
    const float* bias   = nullptr;

    for (int i = 0; i < n_in; ++i) {
        switch (in_sizes[i]) {
            case PM * PK:        x      = (const float*)d_in[i]; break;
            case PKK * PN:       w      = (const int*)  d_in[i]; break;
            case (PK/PG) * PN:   scales = (const float*)d_in[i]; break;
            case PN:             bias   = (const float*)d_in[i]; break;
            default: break; // group_size scalar etc.
        }
    }

    float* out = (float*)d_out;

    dim3 grid(NB, KSPLIT);
    int4gemv_main<<<grid, THREADS>>>(x, w, scales);

    int tot = PM * PN;
    int4gemv_reduce<<<(tot + 255) / 256, 256>>>(bias, out);
}